// round 5
// baseline (speedup 1.0000x reference)
#include <cuda_runtime.h>
#include <cstdint>

#define N_ETA 7
#define FDIM 68
#define HW (512*1024)            // 524288 pixels
#define ESTRIDE 4644             // >= 68*68, mod 32 == 4 -> e*4 bank-group offsets, 7 disjoint 16B groups

__device__ unsigned char g_eta[HW];

// ---------------- threefry2x32 with key (0, 42), exactly as jax._src.prng ----------------
__device__ __forceinline__ void threefry2x32_k42(uint32_t& x0, uint32_t& x1) {
    const uint32_t K2 = 0x1BD11BDAu ^ 0u ^ 42u;
#define TFR(r) { x0 += x1; x1 = __funnelshift_l(x1, x1, (r)); x1 ^= x0; }
    /* x0 += ks[0]=0 */  x1 += 42u;
    TFR(13) TFR(15) TFR(26) TFR(6)
    x0 += 42u;  x1 += K2 + 1u;
    TFR(17) TFR(29) TFR(16) TFR(24)
    x0 += K2;   x1 += 0u + 2u;
    TFR(13) TFR(15) TFR(26) TFR(6)
    /* x0 += 0 */ x1 += 42u + 3u;
    TFR(17) TFR(29) TFR(16) TFR(24)
    x0 += 42u;  x1 += K2 + 4u;
    TFR(13) TFR(15) TFR(26) TFR(6)
    x0 += K2;   x1 += 0u + 5u;
#undef TFR
}

__device__ __forceinline__ float gumbel_from_bits(uint32_t bits) {
    float f = __uint_as_float((bits >> 9) | 0x3F800000u) - 1.0f;  // [0,1), exact
    const float tiny = 1.1754943508222875e-38f;
    float u = fmaxf(tiny, f + tiny);
    return -logf(-logf(u));
}

// Partitionable threefry: element j -> lanes (0, j), output = out0 ^ out1.
__global__ void eta_kernel(const float* __restrict__ T, const int* __restrict__ eta) {
    __shared__ float logT[N_ETA * N_ETA];
    if (threadIdx.x < N_ETA * N_ETA)
        logT[threadIdx.x] = logf(T[threadIdx.x] + 1e-9f);
    __syncthreads();

    int p = blockIdx.x * blockDim.x + threadIdx.x;
    if (p >= HW) return;

    int r = eta[p] * N_ETA;
    float best = -3.0e38f;
    int a = 0;
#pragma unroll
    for (int k = 0; k < N_ETA; k++) {
        uint32_t x0 = 0u;
        uint32_t x1 = (uint32_t)(p * 7 + k);
        threefry2x32_k42(x0, x1);
        uint32_t bits = x0 ^ x1;
        float v = logT[r + k] + gumbel_from_bits(bits);
        if (v > best) { best = v; a = k; }
    }
    g_eta[p] = (unsigned char)a;
}

// ---------------- packed-f32x2 helpers ----------------
__device__ __forceinline__ unsigned long long pack_ff(float x, float y) {
    unsigned long long r;
    asm("mov.b64 %0, {%1, %2};" : "=l"(r) : "f"(x), "f"(y));
    return r;
}
__device__ __forceinline__ void unpack_ff(float& x, float& y, unsigned long long v) {
    asm("mov.b64 {%0, %1}, %2;" : "=f"(x), "=f"(y) : "l"(v));
}
__device__ __forceinline__ void fma2(unsigned long long& acc, unsigned long long w, unsigned long long v) {
    asm("fma.rn.f32x2 %0, %1, %2, %0;" : "+l"(acc) : "l"(w), "l"(v));
}
__device__ __forceinline__ void lds128_b64(unsigned long long& a, unsigned long long& b, const float* p) {
    asm("ld.shared.v2.u64 {%0, %1}, [%2];"
        : "=l"(a), "=l"(b) : "l"(__cvta_generic_to_shared(p)));
}

// out[o,p] = sum_f W[e_p][o][f]*feat[f,p] + b[e_p][o]
// SMEM holds W transposed per expert: Wt[e][f][o]  (o contiguous -> LDS.128 over 4 o's)
__global__ __launch_bounds__(512, 1)
void compute_kernel(const float* __restrict__ feat, const float* __restrict__ W,
                    const float* __restrict__ b, float* __restrict__ out) {
    extern __shared__ float sh[];
    float* Ws = sh;                          // N_ETA * ESTRIDE (transposed)
    float* bs = sh + N_ETA * ESTRIDE;        // N_ETA * FDIM

    // stage W transposed: Ws[e*ESTRIDE + f*FDIM + o] = W[e][o][f]
    for (int i = threadIdx.x; i < N_ETA * FDIM * FDIM; i += blockDim.x) {
        int e = i / (FDIM * FDIM);
        int rem = i - e * FDIM * FDIM;
        int o = rem / FDIM;
        int f = rem - o * FDIM;
        Ws[e * ESTRIDE + f * FDIM + o] = W[i];
    }
    for (int i = threadIdx.x; i < N_ETA * FDIM; i += blockDim.x) bs[i] = b[i];
    __syncthreads();

    const int nchunks = HW / 512;            // 1024
    for (int c = blockIdx.x; c < nchunks; c += gridDim.x) {
        int p = c * 512 + threadIdx.x;
        int e = g_eta[p];
        const float* Wp = Ws + e * ESTRIDE;  // per-lane base: <=7 distinct, disjoint bank groups
        const float* bp = bs + e * FDIM;     // e*68*4 bytes, 16B aligned

        unsigned long long acc[FDIM / 2];
#pragma unroll
        for (int oq = 0; oq < FDIM / 4; oq++)
            lds128_b64(acc[2 * oq], acc[2 * oq + 1], bp + 4 * oq);

#pragma unroll 4
        for (int f = 0; f < FDIM; f++) {
            float v = feat[(size_t)f * HW + p];
            unsigned long long vv = pack_ff(v, v);
            const float* wrow = Wp + f * FDIM;
#pragma unroll
            for (int oq = 0; oq < FDIM / 4; oq++) {
                unsigned long long w01, w23;
                lds128_b64(w01, w23, wrow + 4 * oq);
                fma2(acc[2 * oq], w01, vv);
                fma2(acc[2 * oq + 1], w23, vv);
            }
        }

#pragma unroll
        for (int oq = 0; oq < FDIM / 2; oq++) {
            float x, y;
            unpack_ff(x, y, acc[oq]);
            out[(size_t)(2 * oq)     * HW + p] = x;
            out[(size_t)(2 * oq + 1) * HW + p] = y;
        }
    }
}

extern "C" void kernel_launch(void* const* d_in, const int* in_sizes, int n_in,
                              void* d_out, int out_size) {
    // Resolve inputs by element count (robust to metadata ordering).
    const float* x   = 0;   // 35,651,584
    const float* W   = 0;   // 32,368
    const float* b   = 0;   // 476
    const float* T   = 0;   // 49
    const int*   eta = 0;   // 524,288
    for (int i = 0; i < n_in; i++) {
        switch (in_sizes[i]) {
            case 35651584: x   = (const float*)d_in[i]; break;
            case 32368:    W   = (const float*)d_in[i]; break;
            case 476:      b   = (const float*)d_in[i]; break;
            case 49:       T   = (const float*)d_in[i]; break;
            case 524288:   eta = (const int*)d_in[i];   break;
        }
    }
    float* out = (float*)d_out;                 // [68, HW]

    eta_kernel<<<HW / 256, 256>>>(T, eta);

    int smem = (N_ETA * ESTRIDE + N_ETA * FDIM) * (int)sizeof(float);  // 131,936 B
    cudaFuncSetAttribute(compute_kernel, cudaFuncAttributeMaxDynamicSharedMemorySize, smem);
    int dev = 0, sms = 148;
    cudaGetDevice(&dev);
    cudaDeviceGetAttribute(&sms, cudaDevAttrMultiProcessorCount, dev);
    compute_kernel<<<sms, 512, smem>>>(x, W, b, out);
}